// round 3
// baseline (speedup 1.0000x reference)
#include <cuda_runtime.h>
#include <math.h>

#define HID 512
#define BAT 64
#define SEQ 1024
#define INS 256
#define OUTS 256
#define WROW 768   // INS + HID

// scan partition: 128 CTAs = 16 row-groups x 8 batch-groups
#define NRG 16
#define RPC 32     // rows per CTA
#define BPC 8      // batches per CTA
#define NCTA 128
#define KCH 8      // k-chunks (warps) per CTA
#define KLEN 64    // k elements per chunk
#define NCHUNK 8   // attention seq chunks
#define CHS (SEQ / NCHUNK)

// ---------------- static device scratch (no allocations) --------------------
__device__ float g_xp[(size_t)SEQ * BAT * HID];    // x_proj  [s][b][h]
__device__ float g_hseq[(size_t)BAT * SEQ * HID];  // hidden  [b][s][h]
__device__ float g_h[2][HID * BAT];                // h ping-pong [k][b]
__device__ unsigned g_barv[8 * 32];                // per-batch-group barriers
__device__ float g_sc[BAT * SEQ];                  // scores / attn weights
__device__ float g_ctxp[BAT * NCHUNK * HID];       // context partials

// ---------------- f32x2 helpers ---------------------------------------------
__device__ __forceinline__ unsigned long long f2dup(float a) {
    unsigned long long r;
    asm("mov.b64 %0, {%1, %1};" : "=l"(r) : "f"(a));
    return r;
}
__device__ __forceinline__ void ffma2(unsigned long long& d,
                                      unsigned long long a,
                                      unsigned long long b) {
    asm("fma.rn.f32x2 %0, %1, %2, %0;" : "+l"(d) : "l"(a), "l"(b));
}
__device__ __forceinline__ float2 unpk(unsigned long long a) {
    float2 f;
    asm("mov.b64 {%0, %1}, %2;" : "=f"(f.x), "=f"(f.y) : "l"(a));
    return f;
}

// ---------------- init: zero barriers + h ping-pong --------------------------
__global__ void k_init() {
    int tid = blockIdx.x * blockDim.x + threadIdx.x;
    if (tid < 8 * 32) g_barv[tid] = 0u;
    int n = 2 * HID * BAT;
    float* p = &g_h[0][0];
    for (int i = tid; i < n; i += gridDim.x * blockDim.x) p[i] = 0.0f;
}

// ---------------- GEMM: xp[s][b][h] = sum_i Wx[h][i]*x[b][s][i] + b_ih[h] ---
#define GKC 32
__global__ void __launch_bounds__(256) k_gemm(const float* __restrict__ x,
                                              const float* __restrict__ W,
                                              const float* __restrict__ bih) {
    __shared__ float wxs[GKC][132];  // [k][h within 128-tile]
    __shared__ float xs[GKC][68];    // [k][b]
    const int s  = blockIdx.y;
    const int h0 = blockIdx.x * 128;
    const int tid = threadIdx.x;
    const int bg = tid & 7;    // batch group (8 batches)
    const int hg = tid >> 3;   // h group (4 rows)

    unsigned long long acc[4][4];  // [hh][batch-pair]
#pragma unroll
    for (int i = 0; i < 4; i++)
#pragma unroll
        for (int j = 0; j < 4; j++) acc[i][j] = 0ull;

    for (int c = 0; c < INS; c += GKC) {
        {   // W chunk -> wxs[k][h] (transposed)
            int hh = tid >> 1;
            int kk = (tid & 1) * 16;
            const float* src = W + (size_t)(h0 + hh) * WROW + c + kk;
#pragma unroll
            for (int q = 0; q < 4; q++) {
                float4 v = *(const float4*)(src + q * 4);
                wxs[kk + q * 4 + 0][hh] = v.x;
                wxs[kk + q * 4 + 1][hh] = v.y;
                wxs[kk + q * 4 + 2][hh] = v.z;
                wxs[kk + q * 4 + 3][hh] = v.w;
            }
        }
        {   // x chunk -> xs[k][b] (transposed)
            int bb = tid >> 2;
            int kk = (tid & 3) * 8;
            const float* src = x + ((size_t)bb * SEQ + s) * INS + c + kk;
            float4 a = *(const float4*)(src);
            float4 b4 = *(const float4*)(src + 4);
            xs[kk + 0][bb] = a.x;  xs[kk + 1][bb] = a.y;
            xs[kk + 2][bb] = a.z;  xs[kk + 3][bb] = a.w;
            xs[kk + 4][bb] = b4.x; xs[kk + 5][bb] = b4.y;
            xs[kk + 6][bb] = b4.z; xs[kk + 7][bb] = b4.w;
        }
        __syncthreads();
#pragma unroll 8
        for (int k = 0; k < GKC; k++) {
            float4 w4 = *(const float4*)&wxs[k][hg * 4];
            ulonglong2 xA = *(const ulonglong2*)&xs[k][bg * 8];
            ulonglong2 xB = *(const ulonglong2*)&xs[k][bg * 8 + 4];
            unsigned long long w2[4];
            w2[0] = f2dup(w4.x); w2[1] = f2dup(w4.y);
            w2[2] = f2dup(w4.z); w2[3] = f2dup(w4.w);
#pragma unroll
            for (int hh = 0; hh < 4; hh++) {
                ffma2(acc[hh][0], w2[hh], xA.x);
                ffma2(acc[hh][1], w2[hh], xA.y);
                ffma2(acc[hh][2], w2[hh], xB.x);
                ffma2(acc[hh][3], w2[hh], xB.y);
            }
        }
        __syncthreads();
    }
    // epilogue: +bias, store xp[s][b][h] (h fastest)
    float bi[4];
#pragma unroll
    for (int i = 0; i < 4; i++) bi[i] = bih[h0 + hg * 4 + i];
#pragma unroll
    for (int j = 0; j < 4; j++) {
        float2 p[4];
#pragma unroll
        for (int hh = 0; hh < 4; hh++) p[hh] = unpk(acc[hh][j]);
        int blo = bg * 8 + 2 * j;
        float* d0 = g_xp + ((size_t)s * BAT + blo) * HID + h0 + hg * 4;
        float* d1 = d0 + HID;
        *(float4*)d0 = make_float4(p[0].x + bi[0], p[1].x + bi[1],
                                   p[2].x + bi[2], p[3].x + bi[3]);
        *(float4*)d1 = make_float4(p[0].y + bi[0], p[1].y + bi[1],
                                   p[2].y + bi[2], p[3].y + bi[3]);
    }
}

// ---------------- persistent RNN scan ---------------------------------------
__global__ void __launch_bounds__(256) k_scan(const float* __restrict__ W) {
    __shared__ __align__(16) float h_s[HID][BPC];  // 16 KB, [k][b]
    __shared__ float red[KCH * RPC * 9];           // 9 KB

    const int tid = threadIdx.x;
    const int rg = blockIdx.x & (NRG - 1);
    const int bg = blockIdx.x >> 4;
    const int h0 = rg * RPC;
    const int b0 = bg * BPC;
    const int kc = tid >> 5;   // warp = k-chunk
    const int r  = tid & 31;   // row in tile

    // Wh slice in registers: Wh[h0+r][kc*64 .. +63]
    float w[KLEN];
    {
        const float4* wp =
            (const float4*)(W + (size_t)(h0 + r) * WROW + INS + kc * KLEN);
#pragma unroll
        for (int q = 0; q < 16; q++) {
            float4 v = wp[q];
            w[4 * q + 0] = v.x; w[4 * q + 1] = v.y;
            w[4 * q + 2] = v.z; w[4 * q + 3] = v.w;
        }
    }

    // output role: thread (orr = row, ob = batch)
    const int orr = tid & 31;
    const int ob  = tid >> 5;
    const float* xpp = g_xp + (size_t)(b0 + ob) * HID + (h0 + orr);
    float* hseqp = g_hseq + ((size_t)(b0 + ob) * SEQ) * HID + (h0 + orr);
    unsigned* bar = &g_barv[bg * 32];

    unsigned tgt = 0;
    for (int t = 0; t < SEQ; t++) {
        float xpv = __ldg(xpp + (size_t)t * BAT * HID);

        // load h_{t-1}[0..511][b0..b0+7] -> smem
        const float* gh = g_h[t & 1];
#pragma unroll
        for (int j = 0; j < 4; j++) {
            int c16 = tid + 256 * j;       // 16-byte chunk id (0..1023)
            int k  = c16 >> 1;
            int bo = (c16 & 1) * 4;
            float4 v = *(const float4*)(gh + (size_t)k * BAT + b0 + bo);
            *(float4*)(&h_s[k][bo]) = v;
        }
        __syncthreads();

        // partial matvec over this warp's k-chunk, 8 batches, f32x2
        unsigned long long a0 = 0ull, a1 = 0ull, a2 = 0ull, a3 = 0ull;
        const float* hbase = &h_s[kc * KLEN][0];
#pragma unroll
        for (int j = 0; j < KLEN; j++) {
            ulonglong2 hA = *(const ulonglong2*)(hbase + 8 * j);
            ulonglong2 hB = *(const ulonglong2*)(hbase + 8 * j + 4);
            unsigned long long w2 = f2dup(w[j]);
            ffma2(a0, w2, hA.x);
            ffma2(a1, w2, hA.y);
            ffma2(a2, w2, hB.x);
            ffma2(a3, w2, hB.y);
        }
        {
            float2 f0 = unpk(a0), f1 = unpk(a1), f2v = unpk(a2), f3 = unpk(a3);
            float* rp = &red[(kc * RPC + r) * 9];
            rp[0] = f0.x;  rp[1] = f0.y;  rp[2] = f1.x;  rp[3] = f1.y;
            rp[4] = f2v.x; rp[5] = f2v.y; rp[6] = f3.x;  rp[7] = f3.y;
        }
        __syncthreads();

        // reduce 8 k-chunks, tanh, publish
        float sum = xpv;
#pragma unroll
        for (int c = 0; c < KCH; c++) sum += red[(c * RPC + orr) * 9 + ob];
        float hv = tanhf(sum);
        g_h[(t + 1) & 1][(size_t)(h0 + orr) * BAT + b0 + ob] = hv;
        hseqp[(size_t)t * HID] = hv;

        // per-batch-group release/acquire barrier (16 arrivals)
        __syncthreads();
        tgt += NRG;
        if (tid == 0) {
            __threadfence();
            atomicAdd(bar, 1u);
            unsigned v;
            do {
                asm volatile("ld.acquire.gpu.u32 %0, [%1];"
                             : "=r"(v) : "l"(bar) : "memory");
            } while (v < tgt);
        }
        __syncthreads();
    }
}

// ---------------- attention pass 1: scores ----------------------------------
__global__ void __launch_bounds__(256) k_score() {
    __shared__ float fin[HID];
    const int b  = blockIdx.y;
    const int cs = blockIdx.x;
    const int tid = threadIdx.x;
    const int lane = tid & 31;
    const int wid = tid >> 5;
    const float* hb = g_hseq + (size_t)b * SEQ * HID;

    for (int i = tid; i < HID; i += 256)
        fin[i] = hb[(size_t)(SEQ - 1) * HID + i];
    __syncthreads();

    for (int s0 = wid; s0 < CHS; s0 += 8) {
        int s = cs * CHS + s0;
        const float* row = hb + (size_t)s * HID;
        float p = 0.0f;
#pragma unroll
        for (int q = 0; q < 4; q++) {
            float4 v = *(const float4*)(row + lane * 4 + q * 128);
            float4 f = *(const float4*)(fin + lane * 4 + q * 128);
            p += v.x * f.x + v.y * f.y + v.z * f.z + v.w * f.w;
        }
#pragma unroll
        for (int off = 16; off > 0; off >>= 1)
            p += __shfl_down_sync(0xffffffffu, p, off);
        if (lane == 0) g_sc[(size_t)b * SEQ + s] = p;
    }
}

// ---------------- attention pass 2: softmax over seq -------------------------
__global__ void __launch_bounds__(256) k_softmax() {
    __shared__ float rbuf[256];
    const int b = blockIdx.x;
    const int tid = threadIdx.x;
    float* sc = g_sc + (size_t)b * SEQ;

    float v[4];
#pragma unroll
    for (int q = 0; q < 4; q++) v[q] = sc[tid + q * 256];
    float m = fmaxf(fmaxf(v[0], v[1]), fmaxf(v[2], v[3]));
    rbuf[tid] = m;
    __syncthreads();
    for (int off = 128; off > 0; off >>= 1) {
        if (tid < off) rbuf[tid] = fmaxf(rbuf[tid], rbuf[tid + off]);
        __syncthreads();
    }
    float mx = rbuf[0];
    __syncthreads();
    float ssum = 0.0f;
#pragma unroll
    for (int q = 0; q < 4; q++) { v[q] = expf(v[q] - mx); ssum += v[q]; }
    rbuf[tid] = ssum;
    __syncthreads();
    for (int off = 128; off > 0; off >>= 1) {
        if (tid < off) rbuf[tid] += rbuf[tid + off];
        __syncthreads();
    }
    float inv = 1.0f / rbuf[0];
#pragma unroll
    for (int q = 0; q < 4; q++) sc[tid + q * 256] = v[q] * inv;
}

// ---------------- attention pass 3: chunked context partials -----------------
__global__ void __launch_bounds__(256) k_ctx() {
    __shared__ float at[CHS];
    const int b  = blockIdx.y;
    const int cs = blockIdx.x;
    const int tid = threadIdx.x;
    const float* hb = g_hseq + (size_t)b * SEQ * HID;

    if (tid < CHS) at[tid] = g_sc[(size_t)b * SEQ + cs * CHS + tid];
    __syncthreads();

    float acc0 = 0.0f, acc1 = 0.0f;
    const float* base = hb + (size_t)cs * CHS * HID + 2 * tid;
#pragma unroll 4
    for (int s = 0; s < CHS; s++) {
        float a = at[s];
        float2 hv = *(const float2*)(base + (size_t)s * HID);
        acc0 += a * hv.x;
        acc1 += a * hv.y;
    }
    float* dst = g_ctxp + ((size_t)b * NCHUNK + cs) * HID + 2 * tid;
    *(float2*)dst = make_float2(acc0, acc1);
}

// ---------------- attention pass 4: combine + output projection --------------
__global__ void __launch_bounds__(256) k_out(const float* __restrict__ Who,
                                             const float* __restrict__ bho,
                                             float* __restrict__ out) {
    __shared__ float ctx[HID];
    const int b = blockIdx.x;
    const int tid = threadIdx.x;
    const float* pp = g_ctxp + (size_t)b * NCHUNK * HID;

    for (int h = tid; h < HID; h += 256) {
        float s = 0.0f;
#pragma unroll
        for (int c = 0; c < NCHUNK; c++) s += pp[(size_t)c * HID + h];
        ctx[h] = s;
    }
    __syncthreads();

    int o = tid;
    float acc = bho[o];
    const float4* wp = (const float4*)(Who + (size_t)o * HID);
#pragma unroll 8
    for (int q = 0; q < HID / 4; q++) {
        float4 wv = wp[q];
        const float* cp = &ctx[q * 4];
        acc += wv.x * cp[0] + wv.y * cp[1] + wv.z * cp[2] + wv.w * cp[3];
    }
    out[(size_t)b * OUTS + o] = acc;
}

// ---------------- launch -----------------------------------------------------
extern "C" void kernel_launch(void* const* d_in, const int* in_sizes, int n_in,
                              void* d_out, int out_size) {
    (void)in_sizes; (void)n_in; (void)out_size;
    const float* x    = (const float*)d_in[0];
    const float* W_ih = (const float*)d_in[1];
    const float* b_ih = (const float*)d_in[2];
    const float* W_ho = (const float*)d_in[3];
    const float* b_ho = (const float*)d_in[4];
    float* out = (float*)d_out;

    k_init<<<256, 256>>>();
    k_gemm<<<dim3(4, SEQ), 256>>>(x, W_ih, b_ih);
    k_scan<<<NCTA, 256>>>(W_ih);
    k_score<<<dim3(NCHUNK, BAT), 256>>>();
    k_softmax<<<BAT, 256>>>();
    k_ctx<<<dim3(NCHUNK, BAT), 256>>>();
    k_out<<<BAT, 256>>>(W_ho, b_ho, out);
}

// round 4
// speedup vs baseline: 1.0211x; 1.0211x over previous
#include <cuda_runtime.h>
#include <math.h>
#include <stdint.h>

#define HID 512
#define BAT 64
#define SEQ 1024
#define INS 256
#define OUTS 256
#define WROW 768   // INS + HID

// scan partition: 128 CTAs = 16 clusters (batch groups of 4) x 8 row-group CTAs
#define CLN 8      // CTAs per cluster
#define RPC 64     // rows per CTA
#define BPC 4      // batches per CTA (per cluster)
#define SNT 512    // scan threads per CTA
#define NKC 8      // k-chunks per CTA
#define KLEN 64    // k per chunk

#define NCHUNK 8   // attention seq chunks
#define CHS (SEQ / NCHUNK)

// ---------------- static device scratch (no allocations) --------------------
__device__ float g_xp[(size_t)SEQ * BAT * HID];    // x_proj  [s][b][h]
__device__ float g_hseq[(size_t)BAT * SEQ * HID];  // hidden  [b][s][h]
__device__ float g_sc[BAT * SEQ];                  // scores / attn weights
__device__ float g_ctxp[BAT * NCHUNK * HID];       // context partials

// ---------------- f32x2 helpers ---------------------------------------------
__device__ __forceinline__ unsigned long long f2dup(float a) {
    unsigned long long r;
    asm("mov.b64 %0, {%1, %1};" : "=l"(r) : "f"(a));
    return r;
}
__device__ __forceinline__ void ffma2(unsigned long long& d,
                                      unsigned long long a,
                                      unsigned long long b) {
    asm("fma.rn.f32x2 %0, %1, %2, %0;" : "+l"(d) : "l"(a), "l"(b));
}
__device__ __forceinline__ float2 unpk(unsigned long long a) {
    float2 f;
    asm("mov.b64 {%0, %1}, %2;" : "=f"(f.x), "=f"(f.y) : "l"(a));
    return f;
}
__device__ __forceinline__ uint32_t smem_u32(const void* p) {
    uint32_t a;
    asm("{ .reg .u64 t; cvta.to.shared.u64 t, %1; cvt.u32.u64 %0, t; }"
        : "=r"(a) : "l"(p));
    return a;
}
__device__ __forceinline__ uint32_t mapa_u32(uint32_t addr, uint32_t rank) {
    uint32_t r;
    asm("mapa.shared::cluster.u32 %0, %1, %2;" : "=r"(r) : "r"(addr), "r"(rank));
    return r;
}
__device__ __forceinline__ void st_cluster_v4(uint32_t addr, float4 v) {
    asm volatile("st.shared::cluster.v4.f32 [%0], {%1, %2, %3, %4};"
                 :: "r"(addr), "f"(v.x), "f"(v.y), "f"(v.z), "f"(v.w)
                 : "memory");
}

// ---------------- GEMM: xp[s][b][h] = sum_i Wx[h][i]*x[b][s][i] + b_ih[h] ---
#define GKC 32
__global__ void __launch_bounds__(256) k_gemm(const float* __restrict__ x,
                                              const float* __restrict__ W,
                                              const float* __restrict__ bih) {
    __shared__ float wxs[GKC][132];  // [k][h within 128-tile]
    __shared__ float xs[GKC][68];    // [k][b]
    const int s  = blockIdx.y;
    const int h0 = blockIdx.x * 128;
    const int tid = threadIdx.x;
    const int bg = tid & 7;    // batch group (8 batches)
    const int hg = tid >> 3;   // h group (4 rows)

    unsigned long long acc[4][4];  // [hh][batch-pair]
#pragma unroll
    for (int i = 0; i < 4; i++)
#pragma unroll
        for (int j = 0; j < 4; j++) acc[i][j] = 0ull;

    for (int c = 0; c < INS; c += GKC) {
        {   // W chunk -> wxs[k][h] (transposed)
            int hh = tid >> 1;
            int kk = (tid & 1) * 16;
            const float* src = W + (size_t)(h0 + hh) * WROW + c + kk;
#pragma unroll
            for (int q = 0; q < 4; q++) {
                float4 v = *(const float4*)(src + q * 4);
                wxs[kk + q * 4 + 0][hh] = v.x;
                wxs[kk + q * 4 + 1][hh] = v.y;
                wxs[kk + q * 4 + 2][hh] = v.z;
                wxs[kk + q * 4 + 3][hh] = v.w;
            }
        }
        {   // x chunk -> xs[k][b] (transposed)
            int bb = tid >> 2;
            int kk = (tid & 3) * 8;
            const float* src = x + ((size_t)bb * SEQ + s) * INS + c + kk;
            float4 a = *(const float4*)(src);
            float4 b4 = *(const float4*)(src + 4);
            xs[kk + 0][bb] = a.x;  xs[kk + 1][bb] = a.y;
            xs[kk + 2][bb] = a.z;  xs[kk + 3][bb] = a.w;
            xs[kk + 4][bb] = b4.x; xs[kk + 5][bb] = b4.y;
            xs[kk + 6][bb] = b4.z; xs[kk + 7][bb] = b4.w;
        }
        __syncthreads();
#pragma unroll 8
        for (int k = 0; k < GKC; k++) {
            float4 w4 = *(const float4*)&wxs[k][hg * 4];
            ulonglong2 xA = *(const ulonglong2*)&xs[k][bg * 8];
            ulonglong2 xB = *(const ulonglong2*)&xs[k][bg * 8 + 4];
            unsigned long long w2[4];
            w2[0] = f2dup(w4.x); w2[1] = f2dup(w4.y);
            w2[2] = f2dup(w4.z); w2[3] = f2dup(w4.w);
#pragma unroll
            for (int hh = 0; hh < 4; hh++) {
                ffma2(acc[hh][0], w2[hh], xA.x);
                ffma2(acc[hh][1], w2[hh], xA.y);
                ffma2(acc[hh][2], w2[hh], xB.x);
                ffma2(acc[hh][3], w2[hh], xB.y);
            }
        }
        __syncthreads();
    }
    // epilogue: +bias, store xp[s][b][h] (h fastest)
    float bi[4];
#pragma unroll
    for (int i = 0; i < 4; i++) bi[i] = bih[h0 + hg * 4 + i];
#pragma unroll
    for (int j = 0; j < 4; j++) {
        float2 p[4];
#pragma unroll
        for (int hh = 0; hh < 4; hh++) p[hh] = unpk(acc[hh][j]);
        int blo = bg * 8 + 2 * j;
        float* d0 = g_xp + ((size_t)s * BAT + blo) * HID + h0 + hg * 4;
        float* d1 = d0 + HID;
        *(float4*)d0 = make_float4(p[0].x + bi[0], p[1].x + bi[1],
                                   p[2].x + bi[2], p[3].x + bi[3]);
        *(float4*)d1 = make_float4(p[0].y + bi[0], p[1].y + bi[1],
                                   p[2].y + bi[2], p[3].y + bi[3]);
    }
}

// ---------------- persistent RNN scan: clusters + DSMEM exchange -------------
__global__ void __launch_bounds__(SNT) __cluster_dims__(CLN, 1, 1)
k_scan(const float* __restrict__ W) {
    __shared__ __align__(16) float h_s[2][HID][BPC];  // 16 KB double-buffered
    __shared__ __align__(16) float red[NKC][RPC][8];  // 16 KB (pad 8)

    const int tid = threadIdx.x;
    const int rg = blockIdx.x & (CLN - 1);   // cluster rank = row group
    const int bg = blockIdx.x >> 3;          // batch group (16 groups of 4)
    const int h0 = rg * RPC;
    const int b0 = bg * BPC;
    const int r  = tid & (RPC - 1);          // row within CTA
    const int c  = tid >> 6;                 // k-chunk (0..7)

    // Wh slice in registers: Wh[h0+r][c*64 .. +63]
    float w[KLEN];
    {
        const float4* wp =
            (const float4*)(W + (size_t)(h0 + r) * WROW + INS + c * KLEN);
#pragma unroll
        for (int q = 0; q < 16; q++) {
            float4 v = wp[q];
            w[4 * q + 0] = v.x; w[4 * q + 1] = v.y;
            w[4 * q + 2] = v.z; w[4 * q + 3] = v.w;
        }
    }

    // zero h buffer 0
    for (int i = tid; i < HID * BPC; i += SNT) (&h_s[0][0][0])[i] = 0.0f;

    // peer DSMEM base addresses (fixed rank map; offsets added per step)
    const uint32_t my_hs = smem_u32(&h_s[0][0][0]);
    uint32_t peer[CLN];
#pragma unroll
    for (int k = 0; k < CLN; k++) peer[k] = mapa_u32(my_hs, k);
    __syncthreads();

    const float* xpp = g_xp + (size_t)b0 * HID + (h0 + r);
    float* hseqp = g_hseq + ((size_t)b0 * SEQ) * HID + (h0 + r);

    for (int t = 0; t < SEQ; t++) {
        const int buf = t & 1;

        // prefetch xp for this step (only reduce threads need it)
        float xq[BPC];
        if (tid < RPC) {
            const float* xb = xpp + (size_t)t * BAT * HID;
#pragma unroll
            for (int b = 0; b < BPC; b++) xq[b] = __ldg(xb + (size_t)b * HID);
        }

        // matvec partial: this thread's k-chunk, 4 batches (2 x f32x2)
        unsigned long long a0 = 0ull, a1 = 0ull;
        const float* hb = &h_s[buf][c * KLEN][0];
#pragma unroll
        for (int j = 0; j < KLEN; j++) {
            ulonglong2 hv = *(const ulonglong2*)(hb + 4 * j);
            unsigned long long w2 = f2dup(w[j]);
            ffma2(a0, w2, hv.x);
            ffma2(a1, w2, hv.y);
        }
        {
            float2 p0 = unpk(a0), p1 = unpk(a1);
            *(float4*)&red[c][r][0] = make_float4(p0.x, p0.y, p1.x, p1.y);
        }
        __syncthreads();

        // reduce + tanh + publish (threads 0..63)
        if (tid < RPC) {
            float4 s = make_float4(xq[0], xq[1], xq[2], xq[3]);
#pragma unroll
            for (int c2 = 0; c2 < NKC; c2++) {
                float4 p = *(const float4*)&red[c2][r][0];
                s.x += p.x; s.y += p.y; s.z += p.z; s.w += p.w;
            }
            float4 hv = make_float4(tanhf(s.x), tanhf(s.y),
                                    tanhf(s.z), tanhf(s.w));
            // hseq[b][t][h]
            float* hp = hseqp + (size_t)t * HID;
            hp[0] = hv.x;
            hp[(size_t)SEQ * HID] = hv.y;
            hp[(size_t)2 * SEQ * HID] = hv.z;
            hp[(size_t)3 * SEQ * HID] = hv.w;
            // DSMEM broadcast into peers' next buffer
            uint32_t off = (uint32_t)(((buf ^ 1) * HID + (h0 + r)) * BPC * 4);
#pragma unroll
            for (int k = 0; k < CLN; k++)
                st_cluster_v4(peer[k] + off, hv);
        }

        // cluster barrier: release DSMEM writes, acquire peers'
        asm volatile("barrier.cluster.arrive.aligned;" ::: "memory");
        asm volatile("barrier.cluster.wait.aligned;" ::: "memory");
    }
}

// ---------------- attention pass 1: scores ----------------------------------
__global__ void __launch_bounds__(256) k_score() {
    __shared__ float fin[HID];
    const int b  = blockIdx.y;
    const int cs = blockIdx.x;
    const int tid = threadIdx.x;
    const int lane = tid & 31;
    const int wid = tid >> 5;
    const float* hb = g_hseq + (size_t)b * SEQ * HID;

    for (int i = tid; i < HID; i += 256)
        fin[i] = hb[(size_t)(SEQ - 1) * HID + i];
    __syncthreads();

    for (int s0 = wid; s0 < CHS; s0 += 8) {
        int s = cs * CHS + s0;
        const float* row = hb + (size_t)s * HID;
        float p = 0.0f;
#pragma unroll
        for (int q = 0; q < 4; q++) {
            float4 v = *(const float4*)(row + lane * 4 + q * 128);
            float4 f = *(const float4*)(fin + lane * 4 + q * 128);
            p += v.x * f.x + v.y * f.y + v.z * f.z + v.w * f.w;
        }
#pragma unroll
        for (int off = 16; off > 0; off >>= 1)
            p += __shfl_down_sync(0xffffffffu, p, off);
        if (lane == 0) g_sc[(size_t)b * SEQ + s] = p;
    }
}

// ---------------- attention pass 2: softmax over seq -------------------------
__global__ void __launch_bounds__(256) k_softmax() {
    __shared__ float rbuf[256];
    const int b = blockIdx.x;
    const int tid = threadIdx.x;
    float* sc = g_sc + (size_t)b * SEQ;

    float v[4];
#pragma unroll
    for (int q = 0; q < 4; q++) v[q] = sc[tid + q * 256];
    float m = fmaxf(fmaxf(v[0], v[1]), fmaxf(v[2], v[3]));
    rbuf[tid] = m;
    __syncthreads();
    for (int off = 128; off > 0; off >>= 1) {
        if (tid < off) rbuf[tid] = fmaxf(rbuf[tid], rbuf[tid + off]);
        __syncthreads();
    }
    float mx = rbuf[0];
    __syncthreads();
    float ssum = 0.0f;
#pragma unroll
    for (int q = 0; q < 4; q++) { v[q] = expf(v[q] - mx); ssum += v[q]; }
    rbuf[tid] = ssum;
    __syncthreads();
    for (int off = 128; off > 0; off >>= 1) {
        if (tid < off) rbuf[tid] += rbuf[tid + off];
        __syncthreads();
    }
    float inv = 1.0f / rbuf[0];
#pragma unroll
    for (int q = 0; q < 4; q++) sc[tid + q * 256] = v[q] * inv;
}

// ---------------- attention pass 3: chunked context partials -----------------
__global__ void __launch_bounds__(256) k_ctx() {
    __shared__ float at[CHS];
    const int b  = blockIdx.y;
    const int cs = blockIdx.x;
    const int tid = threadIdx.x;
    const float* hb = g_hseq + (size_t)b * SEQ * HID;

    if (tid < CHS) at[tid] = g_sc[(size_t)b * SEQ + cs * CHS + tid];
    __syncthreads();

    float acc0 = 0.0f, acc1 = 0.0f;
    const float* base = hb + (size_t)cs * CHS * HID + 2 * tid;
#pragma unroll 4
    for (int s = 0; s < CHS; s++) {
        float a = at[s];
        float2 hv = *(const float2*)(base + (size_t)s * HID);
        acc0 += a * hv.x;
        acc1 += a * hv.y;
    }
    float* dst = g_ctxp + ((size_t)b * NCHUNK + cs) * HID + 2 * tid;
    *(float2*)dst = make_float2(acc0, acc1);
}

// ---------------- attention pass 4: combine + output projection --------------
__global__ void __launch_bounds__(256) k_out(const float* __restrict__ Who,
                                             const float* __restrict__ bho,
                                             float* __restrict__ out) {
    __shared__ float ctx[HID];
    const int b = blockIdx.x;
    const int tid = threadIdx.x;
    const float* pp = g_ctxp + (size_t)b * NCHUNK * HID;

    for (int h = tid; h < HID; h += 256) {
        float s = 0.0f;
#pragma unroll
        for (int cc = 0; cc < NCHUNK; cc++) s += pp[(size_t)cc * HID + h];
        ctx[h] = s;
    }
    __syncthreads();

    int o = tid;
    float acc = bho[o];
    const float4* wp = (const float4*)(Who + (size_t)o * HID);
#pragma unroll 8
    for (int q = 0; q < HID / 4; q++) {
        float4 wv = wp[q];
        const float* cp = &ctx[q * 4];
        acc += wv.x * cp[0] + wv.y * cp[1] + wv.z * cp[2] + wv.w * cp[3];
    }
    out[(size_t)b * OUTS + o] = acc;
}

// ---------------- launch -----------------------------------------------------
extern "C" void kernel_launch(void* const* d_in, const int* in_sizes, int n_in,
                              void* d_out, int out_size) {
    (void)in_sizes; (void)n_in; (void)out_size;
    const float* x    = (const float*)d_in[0];
    const float* W_ih = (const float*)d_in[1];
    const float* b_ih = (const float*)d_in[2];
    const float* W_ho = (const float*)d_in[3];
    const float* b_ho = (const float*)d_in[4];
    float* out = (float*)d_out;

    k_gemm<<<dim3(4, SEQ), 256>>>(x, W_ih, b_ih);
    k_scan<<<128, SNT>>>(W_ih);
    k_score<<<dim3(NCHUNK, BAT), 256>>>();
    k_softmax<<<BAT, 256>>>();
    k_ctx<<<dim3(NCHUNK, BAT), 256>>>();
    k_out<<<BAT, 256>>>(W_ho, b_ho, out);
}